// round 16
// baseline (speedup 1.0000x reference)
#include <cuda_runtime.h>
#include <cuda_fp16.h>
#include <stdint.h>

#define NN 32768      // B*M nodes
#define NH 4
#define DD 64
#define BB 64
#define MM 512
#define EE 524288

// ================= device scratch =================
static __device__ float g_q[NN * 256];
static __device__ float g_k[NN * 256];
static __device__ float g_v[NN * 256];
static __device__ __half g_vmeanh[NN * DD];
static __device__ float g_kv[BB * NH * DD * DD];
static __device__ float g_ksum[BB * NH * DD];
static __device__ float g_vsum[BB * NH * DD];
static __device__ int   g_degi[NN];
static __device__ int   g_off[NN + 1];
static __device__ int   g_pos[NN];
static __device__ int   g_erow[EE];
static __device__ float g_ecoef[EE];
static __device__ float g_sumsq[2];
static __device__ __align__(16) __half g_wt[3 * 256 * 256];  // [w][n][k] = fp16(W[k][n])

// ================= init: zero all accumulators =================
#define ZTOT (1048576 + 16384 + 16384 + 32768 + 32768 + 2)
__global__ void init_kernel() {
    int i = blockIdx.x * 256 + threadIdx.x;
    if (i < 1048576) { g_kv[i] = 0.f; return; }
    i -= 1048576;
    if (i < 16384) { g_ksum[i] = 0.f; return; }
    i -= 16384;
    if (i < 16384) { g_vsum[i] = 0.f; return; }
    i -= 16384;
    if (i < 32768) { g_degi[i] = 0; return; }
    i -= 32768;
    if (i < 32768) { g_pos[i] = 0; return; }
    i -= 32768;
    if (i < 2) g_sumsq[i] = 0.f;
}

// ================= W transpose -> fp16 =================
__global__ void wconv_kernel(const float* __restrict__ Wq, const float* __restrict__ Wk,
                             const float* __restrict__ Wv) {
    int w = blockIdx.y, n = blockIdx.x, k = threadIdx.x;
    const float* W = (w == 0) ? Wq : ((w == 1) ? Wk : Wv);
    g_wt[(w * 256 + n) * 256 + k] = __float2half_rn(W[k * 256 + n]);
}

// ================= mma.sync helpers (arch-generic PTX) =================
__device__ __forceinline__ uint32_t smem_u32(const void* p) {
    uint32_t a;
    asm("{ .reg .u64 t; cvta.to.shared.u64 t, %1; cvt.u32.u64 %0, t; }" : "=r"(a) : "l"(p));
    return a;
}
__device__ __forceinline__ void ldmx4(uint32_t* r, uint32_t addr) {
    asm volatile("ldmatrix.sync.aligned.m8n8.x4.shared.b16 {%0,%1,%2,%3}, [%4];"
                 : "=r"(r[0]), "=r"(r[1]), "=r"(r[2]), "=r"(r[3]) : "r"(addr));
}
__device__ __forceinline__ void mma16816(float* d, const uint32_t* a, const uint32_t* b) {
    asm volatile(
        "mma.sync.aligned.m16n8k16.row.col.f32.f16.f16.f32 "
        "{%0,%1,%2,%3}, {%4,%5,%6,%7}, {%8,%9}, {%0,%1,%2,%3};"
        : "+f"(d[0]), "+f"(d[1]), "+f"(d[2]), "+f"(d[3])
        : "r"(a[0]), "r"(a[1]), "r"(a[2]), "r"(a[3]), "r"(b[0]), "r"(b[1]));
}
__device__ __forceinline__ void redg4(float* p, float a, float b, float c, float d) {
    asm volatile("red.global.add.v4.f32 [%0], {%1,%2,%3,%4};"
                 :: "l"(p), "f"(a), "f"(b), "f"(c), "f"(d) : "memory");
}
__device__ __forceinline__ void redg1(float* p, float a) {
    asm volatile("red.global.add.f32 [%0], %1;" :: "l"(p), "f"(a) : "memory");
}

// ================= projection GEMM via tensor cores (R9 exact config) ============
#define SROW 40
__global__ __launch_bounds__(256, 2) void proj_mma_kernel(
    const float* __restrict__ Xq, const float* __restrict__ Xs,
    const float* __restrict__ bq, const float* __restrict__ bk,
    const float* __restrict__ bv)
{
    __shared__ __half Ah[128 * SROW];
    __shared__ __half Bh[128 * SROW];

    const int t = threadIdx.x, lane = t & 31, wid = t >> 5;
    const int wm = wid >> 2, wn = wid & 3;          // 2 x 4 warp grid
    const int y = blockIdx.z;
    const float* A    = (y == 0) ? Xq : Xs;
    const float* bias = (y == 0) ? bq : ((y == 1) ? bk : bv);
    float* C          = (y == 0) ? g_q : ((y == 1) ? g_k : g_v);
    const int sqidx   = (y == 2) ? -1 : y;
    const int row0 = blockIdx.y * 128;
    const int col0 = blockIdx.x * 128;

    const __half* Wt = g_wt + y * 65536;

    const uint32_t ah_b = smem_u32(Ah);
    const uint32_t bh_b = smem_u32(Bh);

    const uint32_t a_lrow = lane & 15, a_lcol = (lane >> 4) * 8;
    const uint32_t b_lrow = lane & 7, b_lcol = (lane >> 3) * 8;

    float acc[4][4][4];
#pragma unroll
    for (int i = 0; i < 4; i++)
#pragma unroll
        for (int j = 0; j < 4; j++)
#pragma unroll
            for (int r = 0; r < 4; r++) acc[i][j][r] = 0.f;

    const int ar = t >> 1, ac = (t & 1);
    const int br2 = t >> 1, bq2 = t & 1;

    for (int kt = 0; kt < 8; kt++) {
        const int k0 = kt * 32;
        __syncthreads();
#pragma unroll
        for (int i = 0; i < 4; i++) {
            int cf = ac * 4 + i;
            float4 a4 = *(const float4*)(A + (size_t)(row0 + ar) * 256 + k0 + cf * 4);
            __half2 p0 = __floats2half2_rn(a4.x, a4.y);
            __half2 p1 = __floats2half2_rn(a4.z, a4.w);
            int o = ar * SROW + cf * 4;
            *(uint2*)&Ah[o] = make_uint2(*(uint32_t*)&p0, *(uint32_t*)&p1);
        }
#pragma unroll
        for (int j = 0; j < 2; j++) {
            int u = bq2 * 2 + j;
            const char* src = (const char*)(Wt + (size_t)(col0 + br2) * 256 + k0) + u * 16;
            int o = br2 * SROW + u * 8;
            *(uint4*)&Bh[o] = *(const uint4*)src;
        }
        __syncthreads();

        uint32_t bhf[4][4];
#pragma unroll
        for (int nf = 0; nf < 4; nf++) {
            uint32_t n = wn * 32 + nf * 8 + b_lrow;
            uint32_t off = (n * SROW + b_lcol) * 2;
            ldmx4(bhf[nf], bh_b + off);
        }
#pragma unroll
        for (int kf = 0; kf < 2; kf++) {
#pragma unroll
            for (int mf = 0; mf < 4; mf++) {
                uint32_t row = wm * 64 + mf * 16 + a_lrow;
                uint32_t off = (row * SROW + kf * 16 + a_lcol) * 2;
                uint32_t ahf[4];
                ldmx4(ahf, ah_b + off);
#pragma unroll
                for (int nf = 0; nf < 4; nf++)
                    mma16816(acc[mf][nf], ahf, &bhf[nf][kf * 2]);
            }
        }
    }

    float ss = 0.f;
    const int rql = lane >> 2, cql = (lane & 3) * 2;
#pragma unroll
    for (int mf = 0; mf < 4; mf++) {
        int r0 = row0 + wm * 64 + mf * 16 + rql;
#pragma unroll
        for (int nf = 0; nf < 4; nf++) {
            int c = col0 + wn * 32 + nf * 8 + cql;
            float b0 = bias[c], b1 = bias[c + 1];
            float v0 = acc[mf][nf][0] + b0, v1 = acc[mf][nf][1] + b1;
            float v2 = acc[mf][nf][2] + b0, v3 = acc[mf][nf][3] + b1;
            ss += v0 * v0 + v1 * v1 + v2 * v2 + v3 * v3;
            *(float2*)(C + (size_t)r0 * 256 + c)       = make_float2(v0, v1);
            *(float2*)(C + (size_t)(r0 + 8) * 256 + c) = make_float2(v2, v3);
        }
    }
    if (sqidx >= 0) {
#pragma unroll
        for (int o = 16; o > 0; o >>= 1) ss += __shfl_down_sync(0xffffffffu, ss, o);
        if (lane == 0) atomicAdd(&g_sumsq[sqidx], ss);
    }
}

// ================= degree (int counts) =================
__global__ void deg_kernel(const int* __restrict__ ei) {
    int e = blockIdx.x * 256 + threadIdx.x;
    if (e < EE) atomicAdd(&g_degi[ei[EE + e]], 1);
}

// ================= exclusive scan of degi -> off (single block, 1024 thr) =======
__global__ __launch_bounds__(1024) void scan_kernel() {
    __shared__ int wsum[32];
    int t = threadIdx.x;
    int lane = t & 31, wid = t >> 5;
    int loc[32];
    int base = t * 32;
    int s = 0;
#pragma unroll
    for (int i = 0; i < 8; i++) {
        int4 v4 = *(const int4*)(g_degi + base + i * 4);
        loc[i * 4 + 0] = v4.x; loc[i * 4 + 1] = v4.y;
        loc[i * 4 + 2] = v4.z; loc[i * 4 + 3] = v4.w;
        s += v4.x + v4.y + v4.z + v4.w;
    }
    int v = s;
#pragma unroll
    for (int o = 1; o < 32; o <<= 1) {
        int n = __shfl_up_sync(0xffffffffu, v, o);
        if (lane >= o) v += n;
    }
    if (lane == 31) wsum[wid] = v;
    __syncthreads();
    if (wid == 0) {
        int w = wsum[lane];
#pragma unroll
        for (int o = 1; o < 32; o <<= 1) {
            int n = __shfl_up_sync(0xffffffffu, w, o);
            if (lane >= o) w += n;
        }
        wsum[lane] = w;      // inclusive warp totals
    }
    __syncthreads();
    int run = v - s + (wid > 0 ? wsum[wid - 1] : 0);   // exclusive prefix for this thread
#pragma unroll
    for (int i = 0; i < 32; i++) { g_off[base + i] = run; run += loc[i]; }
    if (t == 1023) g_off[NN] = run;
}

// ================= CSR fill: bucket (row, coeff) per destination col ============
__global__ void fill_kernel(const int* __restrict__ ei, const float* __restrict__ ew) {
    int e = blockIdx.x * 256 + threadIdx.x;
    if (e >= EE) return;
    int row = ei[e];
    int col = ei[EE + e];
    int idx = g_off[col] + atomicAdd(&g_pos[col], 1);
    int pr = g_degi[col] * g_degi[row];
    g_erow[idx]  = row;
    g_ecoef[idx] = (pr > 0) ? ew[e] * rsqrtf((float)pr) : 0.f;
}

// ================= head-mean of v -> fp16 =================
__global__ void vmean_kernel() {
    int i = blockIdx.x * 256 + threadIdx.x;    // NN*32 threads
    int n = i >> 5, dp = (i & 31) * 2;
    const float* vr = g_v + (size_t)n * 256 + dp;
    float2 a0 = *(const float2*)(vr);
    float2 a1 = *(const float2*)(vr + 64);
    float2 a2 = *(const float2*)(vr + 128);
    float2 a3 = *(const float2*)(vr + 192);
    float x = 0.25f * (a0.x + a1.x + a2.x + a3.x);
    float y = 0.25f * (a0.y + a1.y + a2.y + a3.y);
    *(__half2*)(g_vmeanh + (size_t)n * 64 + dp) = __floats2half2_rn(x, y);
}

// ================= per (b,h,mchunk): kv, ksum, vsum partials via red.global =====
__global__ __launch_bounds__(256) void kv_kernel() {
    int bh = blockIdx.x, mc = blockIdx.y;
    int b = bh >> 2, h = bh & 3;
    __shared__ float ks[8][64], vs[8][64];
    int t = threadIdx.x;
    int ty = t >> 4, tx = t & 15;
    float acc[4][4] = {};
    float s1 = 0.f, s2 = 0.f;
    const float* kb = g_k + (size_t)b * 512 * 256 + (size_t)mc * 128 * 256 + h * 64;
    const float* vb = g_v + (size_t)b * 512 * 256 + (size_t)mc * 128 * 256 + h * 64;

    for (int m0 = 0; m0 < 128; m0 += 8) {
#pragma unroll
        for (int j = 0; j < 2; j++) {
            int i = t + j * 256;
            int r = i >> 6, c2 = i & 63;
            ks[r][c2] = kb[(size_t)(m0 + r) * 256 + c2];
            vs[r][c2] = vb[(size_t)(m0 + r) * 256 + c2];
        }
        __syncthreads();
#pragma unroll
        for (int r = 0; r < 8; r++) {
            float kr[4], vr[4];
            float4 k4 = *(const float4*)&ks[r][ty * 4];
            float4 v4 = *(const float4*)&vs[r][tx * 4];
            kr[0]=k4.x; kr[1]=k4.y; kr[2]=k4.z; kr[3]=k4.w;
            vr[0]=v4.x; vr[1]=v4.y; vr[2]=v4.z; vr[3]=v4.w;
#pragma unroll
            for (int i = 0; i < 4; i++)
#pragma unroll
                for (int j = 0; j < 4; j++)
                    acc[i][j] = fmaf(kr[i], vr[j], acc[i][j]);
        }
        if (t < 64) {
#pragma unroll
            for (int r = 0; r < 8; r++) s1 += ks[r][t];
        } else if (t < 128) {
#pragma unroll
            for (int r = 0; r < 8; r++) s2 += vs[r][t - 64];
        }
        __syncthreads();
    }
    float* kvout = g_kv + (size_t)bh * 4096;
#pragma unroll
    for (int i = 0; i < 4; i++)
        redg4(kvout + (ty * 4 + i) * 64 + tx * 4, acc[i][0], acc[i][1], acc[i][2], acc[i][3]);
    if (t < 64) redg1(g_ksum + bh * 64 + t, s1);
    else if (t < 128) redg1(g_vsum + bh * 64 + (t - 64), s2);
}

// ================= fused attention output: P=Q@KV, den, combine -> out ==========
#define QS_STRIDE 36
#define ATT_FLOATS (9216 + 16384 + 256 + 256 + 128)
#define ATT_SMEM (ATT_FLOATS * 4)
__global__ __launch_bounds__(256, 2) void att_kernel(const int* __restrict__ nnodes,
                                                     float* __restrict__ out) {
    extern __shared__ float sm[];
    float* Qs   = sm;                    // [h][k][m] stride QS_STRIDE
    float* KVs  = sm + 9216;             // [h][k*64+d]
    float* ksum = sm + 9216 + 16384;
    float* vsum = ksum + 256;
    float* dens = vsum + 256;            // [m][h], m in 0..31

    const int t = threadIdx.x;
    const int b = blockIdx.x, chunk = blockIdx.y;
    const int n0 = b * 512 + chunk * 32;

    {
        const float* qb = g_q + (size_t)n0 * 256;
        int la_m = t >> 3;
        int cb0 = (t & 7) * 4;
#pragma unroll
        for (int j = 0; j < 8; j++) {
            int c = cb0 + j * 32;
            int h = c >> 6, kk = c & 63;
            float4 v4 = *(const float4*)(qb + (size_t)la_m * 256 + c);
            float* Qh = Qs + h * (64 * QS_STRIDE);
            Qh[(kk + 0) * QS_STRIDE + la_m] = v4.x;
            Qh[(kk + 1) * QS_STRIDE + la_m] = v4.y;
            Qh[(kk + 2) * QS_STRIDE + la_m] = v4.z;
            Qh[(kk + 3) * QS_STRIDE + la_m] = v4.w;
        }
    }
    {
        const float* kvb = g_kv + (size_t)b * 16384;
#pragma unroll
        for (int j = 0; j < 16; j++)
            *(float4*)&KVs[(t + j * 256) * 4] = *(const float4*)(kvb + (t + j * 256) * 4);
        ksum[t] = g_ksum[b * 256 + t];
        vsum[t] = g_vsum[b * 256 + t];
    }
    __syncthreads();

    if (t < 128) {
        int h = t >> 5, m = t & 31;
        const float* Qh = Qs + h * (64 * QS_STRIDE);
        const float* kh = ksum + h * 64;
        float p = 0.f;
#pragma unroll
        for (int k = 0; k < 64; k++) p = fmaf(Qh[k * QS_STRIDE + m], kh[k], p);
        dens[m * 4 + h] = p;
    }
    __syncthreads();

    const float s = rsqrtf(g_sumsq[0]) * rsqrtf(g_sumsq[1]);
    const float nnv = (float)nnodes[b];
    const int rm0 = (t >> 4) * 2, cn0 = (t & 15) * 4;

    float o[2][4];
#pragma unroll
    for (int i = 0; i < 2; i++)
#pragma unroll
        for (int j = 0; j < 4; j++) o[i][j] = 0.f;

#pragma unroll
    for (int h = 0; h < 4; h++) {
        const float* Qh = Qs + h * (64 * QS_STRIDE);
        const float* KVh = KVs + h * 4096;
        float acc[2][4] = {};
#pragma unroll
        for (int k = 0; k < 64; k++) {
            float2 qa = *(const float2*)&Qh[k * QS_STRIDE + rm0];
            float4 t1 = *(const float4*)&KVh[k * 64 + cn0];
            acc[0][0] = fmaf(qa.x, t1.x, acc[0][0]);
            acc[0][1] = fmaf(qa.x, t1.y, acc[0][1]);
            acc[0][2] = fmaf(qa.x, t1.z, acc[0][2]);
            acc[0][3] = fmaf(qa.x, t1.w, acc[0][3]);
            acc[1][0] = fmaf(qa.y, t1.x, acc[1][0]);
            acc[1][1] = fmaf(qa.y, t1.y, acc[1][1]);
            acc[1][2] = fmaf(qa.y, t1.z, acc[1][2]);
            acc[1][3] = fmaf(qa.y, t1.w, acc[1][3]);
        }
#pragma unroll
        for (int i = 0; i < 2; i++) {
            float inv = 1.0f / fmaf(s, dens[(rm0 + i) * 4 + h], nnv);
#pragma unroll
            for (int j = 0; j < 4; j++)
                o[i][j] += fmaf(s, acc[i][j], vsum[h * 64 + cn0 + j]) * inv;
        }
    }
#pragma unroll
    for (int i = 0; i < 2; i++)
        *(float4*)(out + (size_t)(n0 + rm0 + i) * 64 + cn0) =
            make_float4(0.25f * o[i][0], 0.25f * o[i][1], 0.25f * o[i][2], 0.25f * o[i][3]);
}

// ================= GCN via CSR gather: warp per destination node ================
__global__ __launch_bounds__(256) void gcn_kernel(float* __restrict__ out) {
    int w = (blockIdx.x * 256 + threadIdx.x) >> 5;   // node (col)
    int lane = threadIdx.x & 31;
    int s = g_off[w], e = g_off[w + 1];
    float ax = 0.f, ay = 0.f;
    int j = s;
    for (; j + 4 <= e; j += 4) {
        int   r0 = g_erow[j],     r1 = g_erow[j + 1], r2 = g_erow[j + 2], r3 = g_erow[j + 3];
        float c0 = g_ecoef[j],    c1 = g_ecoef[j + 1], c2 = g_ecoef[j + 2], c3 = g_ecoef[j + 3];
        float2 f0 = __half22float2(*(const __half2*)(g_vmeanh + (size_t)r0 * 64 + lane * 2));
        float2 f1 = __half22float2(*(const __half2*)(g_vmeanh + (size_t)r1 * 64 + lane * 2));
        float2 f2 = __half22float2(*(const __half2*)(g_vmeanh + (size_t)r2 * 64 + lane * 2));
        float2 f3 = __half22float2(*(const __half2*)(g_vmeanh + (size_t)r3 * 64 + lane * 2));
        ax = fmaf(c0, f0.x, ax); ay = fmaf(c0, f0.y, ay);
        ax = fmaf(c1, f1.x, ax); ay = fmaf(c1, f1.y, ay);
        ax = fmaf(c2, f2.x, ax); ay = fmaf(c2, f2.y, ay);
        ax = fmaf(c3, f3.x, ax); ay = fmaf(c3, f3.y, ay);
    }
    for (; j < e; j++) {
        int row = g_erow[j];
        float cf = g_ecoef[j];
        float2 f = __half22float2(*(const __half2*)(g_vmeanh + (size_t)row * 64 + lane * 2));
        ax = fmaf(cf, f.x, ax); ay = fmaf(cf, f.y, ay);
    }
    float2* po = (float2*)(out + (size_t)w * 64 + lane * 2);
    float2 c = *po;
    c.x += ax; c.y += ay;
    *po = c;
}

extern "C" void kernel_launch(void* const* d_in, const int* in_sizes, int n_in,
                              void* d_out, int out_size) {
    const float* Xq = (const float*)d_in[0];
    const float* Xs = (const float*)d_in[1];
    const float* ew = (const float*)d_in[2];
    const float* Wq = (const float*)d_in[3];
    const float* bq = (const float*)d_in[4];
    const float* Wk = (const float*)d_in[5];
    const float* bk = (const float*)d_in[6];
    const float* Wv = (const float*)d_in[7];
    const float* bv = (const float*)d_in[8];
    const int*   nn = (const int*)d_in[9];
    const int*   ei = (const int*)d_in[10];
    float* out = (float*)d_out;

    cudaFuncSetAttribute(att_kernel, cudaFuncAttributeMaxDynamicSharedMemorySize, ATT_SMEM);

    // order keeps proj in the ncu capture window (launch index 3)
    init_kernel<<<(ZTOT + 255) / 256, 256>>>();
    wconv_kernel<<<dim3(256, 3), 256>>>(Wq, Wk, Wv);
    deg_kernel<<<EE / 256, 256>>>(ei);
    proj_mma_kernel<<<dim3(2, 256, 3), 256>>>(Xq, Xs, bq, bk, bv);
    scan_kernel<<<1, 1024>>>();
    fill_kernel<<<EE / 256, 256>>>(ei, ew);
    vmean_kernel<<<(NN * 32) / 256, 256>>>();
    kv_kernel<<<dim3(BB * NH, 4), 256>>>();
    att_kernel<<<dim3(BB, 16), 256, ATT_SMEM>>>(nn, out);
    gcn_kernel<<<(NN * 32) / 256, 256>>>(out);
}

// round 17
// speedup vs baseline: 1.0596x; 1.0596x over previous
#include <cuda_runtime.h>
#include <cuda_fp16.h>
#include <stdint.h>

#define NN 32768      // B*M nodes
#define NH 4
#define DD 64
#define BB 64
#define MM 512
#define EE 524288

// ================= device scratch =================
static __device__ float g_q[NN * 256];
static __device__ float g_k[NN * 256];
static __device__ float g_v[NN * 256];
static __device__ __half g_vmeanh[NN * DD];
static __device__ float g_kv[BB * NH * DD * DD];
static __device__ float g_ksum[BB * NH * DD];
static __device__ float g_vsum[BB * NH * DD];
static __device__ float g_deg[NN];
static __device__ float g_sumsq[2];
static __device__ __align__(16) __half g_wt[3 * 256 * 256];  // [w][n][k] = fp16(W[k][n])

// ================= init: zero all accumulators =================
#define ZTOT (1048576 + 16384 + 16384 + 32768 + 2)
__global__ void init_kernel() {
    int i = blockIdx.x * 256 + threadIdx.x;
    if (i < 1048576) { g_kv[i] = 0.f; return; }
    i -= 1048576;
    if (i < 16384) { g_ksum[i] = 0.f; return; }
    i -= 16384;
    if (i < 16384) { g_vsum[i] = 0.f; return; }
    i -= 16384;
    if (i < 32768) { g_deg[i] = 0.f; return; }
    i -= 32768;
    if (i < 2) g_sumsq[i] = 0.f;
}

// ================= W transpose -> fp16 =================
__global__ void wconv_kernel(const float* __restrict__ Wq, const float* __restrict__ Wk,
                             const float* __restrict__ Wv) {
    int w = blockIdx.y, n = blockIdx.x, k = threadIdx.x;
    const float* W = (w == 0) ? Wq : ((w == 1) ? Wk : Wv);
    g_wt[(w * 256 + n) * 256 + k] = __float2half_rn(W[k * 256 + n]);
}

// ================= mma.sync helpers (arch-generic PTX) =================
__device__ __forceinline__ uint32_t smem_u32(const void* p) {
    uint32_t a;
    asm("{ .reg .u64 t; cvta.to.shared.u64 t, %1; cvt.u32.u64 %0, t; }" : "=r"(a) : "l"(p));
    return a;
}
__device__ __forceinline__ void ldmx4(uint32_t* r, uint32_t addr) {
    asm volatile("ldmatrix.sync.aligned.m8n8.x4.shared.b16 {%0,%1,%2,%3}, [%4];"
                 : "=r"(r[0]), "=r"(r[1]), "=r"(r[2]), "=r"(r[3]) : "r"(addr));
}
__device__ __forceinline__ void mma16816(float* d, const uint32_t* a, const uint32_t* b) {
    asm volatile(
        "mma.sync.aligned.m16n8k16.row.col.f32.f16.f16.f32 "
        "{%0,%1,%2,%3}, {%4,%5,%6,%7}, {%8,%9}, {%0,%1,%2,%3};"
        : "+f"(d[0]), "+f"(d[1]), "+f"(d[2]), "+f"(d[3])
        : "r"(a[0]), "r"(a[1]), "r"(a[2]), "r"(a[3]), "r"(b[0]), "r"(b[1]));
}
__device__ __forceinline__ void redg4(float* p, float a, float b, float c, float d) {
    asm volatile("red.global.add.v4.f32 [%0], {%1,%2,%3,%4};"
                 :: "l"(p), "f"(a), "f"(b), "f"(c), "f"(d) : "memory");
}
__device__ __forceinline__ void redg1(float* p, float a) {
    asm volatile("red.global.add.f32 [%0], %1;" :: "l"(p), "f"(a) : "memory");
}

// ================= projection GEMM via tensor cores (R9 exact config) ============
// grid (2, 256, 3), CTA tile 128x128, BK=32, 8 warps (2x4), warp tile 64x32.
#define SROW 40
__global__ __launch_bounds__(256, 2) void proj_mma_kernel(
    const float* __restrict__ Xq, const float* __restrict__ Xs,
    const float* __restrict__ bq, const float* __restrict__ bk,
    const float* __restrict__ bv)
{
    __shared__ __half Ah[128 * SROW];
    __shared__ __half Bh[128 * SROW];

    const int t = threadIdx.x, lane = t & 31, wid = t >> 5;
    const int wm = wid >> 2, wn = wid & 3;          // 2 x 4 warp grid
    const int y = blockIdx.z;
    const float* A    = (y == 0) ? Xq : Xs;
    const float* bias = (y == 0) ? bq : ((y == 1) ? bk : bv);
    float* C          = (y == 0) ? g_q : ((y == 1) ? g_k : g_v);
    const int sqidx   = (y == 2) ? -1 : y;
    const int row0 = blockIdx.y * 128;
    const int col0 = blockIdx.x * 128;

    const __half* Wt = g_wt + y * 65536;

    const uint32_t ah_b = smem_u32(Ah);
    const uint32_t bh_b = smem_u32(Bh);

    const uint32_t a_lrow = lane & 15, a_lcol = (lane >> 4) * 8;
    const uint32_t b_lrow = lane & 7, b_lcol = (lane >> 3) * 8;

    float acc[4][4][4];
#pragma unroll
    for (int i = 0; i < 4; i++)
#pragma unroll
        for (int j = 0; j < 4; j++)
#pragma unroll
            for (int r = 0; r < 4; r++) acc[i][j][r] = 0.f;

    const int ar = t >> 1, ac = (t & 1);
    const int br2 = t >> 1, bq2 = t & 1;

    for (int kt = 0; kt < 8; kt++) {
        const int k0 = kt * 32;
        __syncthreads();
#pragma unroll
        for (int i = 0; i < 4; i++) {
            int cf = ac * 4 + i;
            float4 a4 = *(const float4*)(A + (size_t)(row0 + ar) * 256 + k0 + cf * 4);
            __half2 p0 = __floats2half2_rn(a4.x, a4.y);
            __half2 p1 = __floats2half2_rn(a4.z, a4.w);
            int o = ar * SROW + cf * 4;
            *(uint2*)&Ah[o] = make_uint2(*(uint32_t*)&p0, *(uint32_t*)&p1);
        }
#pragma unroll
        for (int j = 0; j < 2; j++) {
            int u = bq2 * 2 + j;
            const char* src = (const char*)(Wt + (size_t)(col0 + br2) * 256 + k0) + u * 16;
            int o = br2 * SROW + u * 8;
            *(uint4*)&Bh[o] = *(const uint4*)src;
        }
        __syncthreads();

        uint32_t bhf[4][4];
#pragma unroll
        for (int nf = 0; nf < 4; nf++) {
            uint32_t n = wn * 32 + nf * 8 + b_lrow;
            uint32_t off = (n * SROW + b_lcol) * 2;
            ldmx4(bhf[nf], bh_b + off);
        }
#pragma unroll
        for (int kf = 0; kf < 2; kf++) {
#pragma unroll
            for (int mf = 0; mf < 4; mf++) {
                uint32_t row = wm * 64 + mf * 16 + a_lrow;
                uint32_t off = (row * SROW + kf * 16 + a_lcol) * 2;
                uint32_t ahf[4];
                ldmx4(ahf, ah_b + off);
#pragma unroll
                for (int nf = 0; nf < 4; nf++)
                    mma16816(acc[mf][nf], ahf, &bhf[nf][kf * 2]);
            }
        }
    }

    float ss = 0.f;
    const int rql = lane >> 2, cql = (lane & 3) * 2;
#pragma unroll
    for (int mf = 0; mf < 4; mf++) {
        int r0 = row0 + wm * 64 + mf * 16 + rql;
#pragma unroll
        for (int nf = 0; nf < 4; nf++) {
            int c = col0 + wn * 32 + nf * 8 + cql;
            float b0 = bias[c], b1 = bias[c + 1];
            float v0 = acc[mf][nf][0] + b0, v1 = acc[mf][nf][1] + b1;
            float v2 = acc[mf][nf][2] + b0, v3 = acc[mf][nf][3] + b1;
            ss += v0 * v0 + v1 * v1 + v2 * v2 + v3 * v3;
            *(float2*)(C + (size_t)r0 * 256 + c)       = make_float2(v0, v1);
            *(float2*)(C + (size_t)(r0 + 8) * 256 + c) = make_float2(v2, v3);
        }
    }
    if (sqidx >= 0) {
#pragma unroll
        for (int o = 16; o > 0; o >>= 1) ss += __shfl_down_sync(0xffffffffu, ss, o);
        if (lane == 0) atomicAdd(&g_sumsq[sqidx], ss);
    }
}

// ================= degree =================
__global__ void deg_kernel(const int* __restrict__ ei) {
    int e = blockIdx.x * 256 + threadIdx.x;
    if (e < EE) atomicAdd(&g_deg[ei[EE + e]], 1.0f);
}

// ================= per (b,h,mchunk): kv, ksum, vsum partials via red.global =====
__global__ __launch_bounds__(256) void kv_kernel() {
    int bh = blockIdx.x, mc = blockIdx.y;
    int b = bh >> 2, h = bh & 3;
    __shared__ float ks[8][64], vs[8][64];
    int t = threadIdx.x;
    int ty = t >> 4, tx = t & 15;
    float acc[4][4] = {};
    float s1 = 0.f, s2 = 0.f;
    const float* kb = g_k + (size_t)b * 512 * 256 + (size_t)mc * 128 * 256 + h * 64;
    const float* vb = g_v + (size_t)b * 512 * 256 + (size_t)mc * 128 * 256 + h * 64;

    for (int m0 = 0; m0 < 128; m0 += 8) {
#pragma unroll
        for (int j = 0; j < 2; j++) {
            int i = t + j * 256;
            int r = i >> 6, c2 = i & 63;
            ks[r][c2] = kb[(size_t)(m0 + r) * 256 + c2];
            vs[r][c2] = vb[(size_t)(m0 + r) * 256 + c2];
        }
        __syncthreads();
#pragma unroll
        for (int r = 0; r < 8; r++) {
            float kr[4], vr[4];
            float4 k4 = *(const float4*)&ks[r][ty * 4];
            float4 v4 = *(const float4*)&vs[r][tx * 4];
            kr[0]=k4.x; kr[1]=k4.y; kr[2]=k4.z; kr[3]=k4.w;
            vr[0]=v4.x; vr[1]=v4.y; vr[2]=v4.z; vr[3]=v4.w;
#pragma unroll
            for (int i = 0; i < 4; i++)
#pragma unroll
                for (int j = 0; j < 4; j++)
                    acc[i][j] = fmaf(kr[i], vr[j], acc[i][j]);
        }
        if (t < 64) {
#pragma unroll
            for (int r = 0; r < 8; r++) s1 += ks[r][t];
        } else if (t < 128) {
#pragma unroll
            for (int r = 0; r < 8; r++) s2 += vs[r][t - 64];
        }
        __syncthreads();
    }
    float* kvout = g_kv + (size_t)bh * 4096;
#pragma unroll
    for (int i = 0; i < 4; i++)
        redg4(kvout + (ty * 4 + i) * 64 + tx * 4, acc[i][0], acc[i][1], acc[i][2], acc[i][3]);
    if (t < 64) redg1(g_ksum + bh * 64 + t, s1);
    else if (t < 128) redg1(g_vsum + bh * 64 + (t - 64), s2);
}

// ================= fused attention output (+ vmean prologue) =====================
// grid = (64, 16): b, 32-row chunk. vmean for these 32 nodes computed up front
// (gcn consumes g_vmeanh and runs strictly after att).
#define QS_STRIDE 36
#define ATT_FLOATS (9216 + 16384 + 256 + 256 + 128)
#define ATT_SMEM (ATT_FLOATS * 4)
__global__ __launch_bounds__(256, 2) void att_kernel(const int* __restrict__ nnodes,
                                                     float* __restrict__ out) {
    extern __shared__ float sm[];
    float* Qs   = sm;                    // [h][k][m] stride QS_STRIDE
    float* KVs  = sm + 9216;             // [h][k*64+d]
    float* ksum = sm + 9216 + 16384;
    float* vsum = ksum + 256;
    float* dens = vsum + 256;            // [m][h], m in 0..31

    const int t = threadIdx.x;
    const int b = blockIdx.x, chunk = blockIdx.y;
    const int n0 = b * 512 + chunk * 32;

    // ---- vmean prologue: 32 nodes x 64 d -> fp16, 8 d per thread ----
    {
        int n = n0 + (t >> 3);
        int d0 = (t & 7) * 8;
        const float* vr = g_v + (size_t)n * 256 + d0;
        float4 h0a = *(const float4*)(vr),       h0b = *(const float4*)(vr + 4);
        float4 h1a = *(const float4*)(vr + 64),  h1b = *(const float4*)(vr + 68);
        float4 h2a = *(const float4*)(vr + 128), h2b = *(const float4*)(vr + 132);
        float4 h3a = *(const float4*)(vr + 192), h3b = *(const float4*)(vr + 196);
        __half2 o0 = __floats2half2_rn(0.25f * (h0a.x + h1a.x + h2a.x + h3a.x),
                                       0.25f * (h0a.y + h1a.y + h2a.y + h3a.y));
        __half2 o1 = __floats2half2_rn(0.25f * (h0a.z + h1a.z + h2a.z + h3a.z),
                                       0.25f * (h0a.w + h1a.w + h2a.w + h3a.w));
        __half2 o2 = __floats2half2_rn(0.25f * (h0b.x + h1b.x + h2b.x + h3b.x),
                                       0.25f * (h0b.y + h1b.y + h2b.y + h3b.y));
        __half2 o3 = __floats2half2_rn(0.25f * (h0b.z + h1b.z + h2b.z + h3b.z),
                                       0.25f * (h0b.w + h1b.w + h2b.w + h3b.w));
        *(uint4*)(g_vmeanh + (size_t)n * 64 + d0) =
            make_uint4(*(uint32_t*)&o0, *(uint32_t*)&o1, *(uint32_t*)&o2, *(uint32_t*)&o3);
    }

    {
        const float* qb = g_q + (size_t)n0 * 256;
        int la_m = t >> 3;
        int cb0 = (t & 7) * 4;
#pragma unroll
        for (int j = 0; j < 8; j++) {
            int c = cb0 + j * 32;
            int h = c >> 6, kk = c & 63;
            float4 v4 = *(const float4*)(qb + (size_t)la_m * 256 + c);
            float* Qh = Qs + h * (64 * QS_STRIDE);
            Qh[(kk + 0) * QS_STRIDE + la_m] = v4.x;
            Qh[(kk + 1) * QS_STRIDE + la_m] = v4.y;
            Qh[(kk + 2) * QS_STRIDE + la_m] = v4.z;
            Qh[(kk + 3) * QS_STRIDE + la_m] = v4.w;
        }
    }
    {
        const float* kvb = g_kv + (size_t)b * 16384;
#pragma unroll
        for (int j = 0; j < 16; j++)
            *(float4*)&KVs[(t + j * 256) * 4] = *(const float4*)(kvb + (t + j * 256) * 4);
        ksum[t] = g_ksum[b * 256 + t];
        vsum[t] = g_vsum[b * 256 + t];
    }
    __syncthreads();

    if (t < 128) {
        int h = t >> 5, m = t & 31;
        const float* Qh = Qs + h * (64 * QS_STRIDE);
        const float* kh = ksum + h * 64;
        float p = 0.f;
#pragma unroll
        for (int k = 0; k < 64; k++) p = fmaf(Qh[k * QS_STRIDE + m], kh[k], p);
        dens[m * 4 + h] = p;
    }
    __syncthreads();

    const float s = rsqrtf(g_sumsq[0]) * rsqrtf(g_sumsq[1]);
    const float nnv = (float)nnodes[b];
    const int rm0 = (t >> 4) * 2, cn0 = (t & 15) * 4;

    float o[2][4];
#pragma unroll
    for (int i = 0; i < 2; i++)
#pragma unroll
        for (int j = 0; j < 4; j++) o[i][j] = 0.f;

#pragma unroll
    for (int h = 0; h < 4; h++) {
        const float* Qh = Qs + h * (64 * QS_STRIDE);
        const float* KVh = KVs + h * 4096;
        float acc[2][4] = {};
#pragma unroll
        for (int k = 0; k < 64; k++) {
            float2 qa = *(const float2*)&Qh[k * QS_STRIDE + rm0];
            float4 t1 = *(const float4*)&KVh[k * 64 + cn0];
            acc[0][0] = fmaf(qa.x, t1.x, acc[0][0]);
            acc[0][1] = fmaf(qa.x, t1.y, acc[0][1]);
            acc[0][2] = fmaf(qa.x, t1.z, acc[0][2]);
            acc[0][3] = fmaf(qa.x, t1.w, acc[0][3]);
            acc[1][0] = fmaf(qa.y, t1.x, acc[1][0]);
            acc[1][1] = fmaf(qa.y, t1.y, acc[1][1]);
            acc[1][2] = fmaf(qa.y, t1.z, acc[1][2]);
            acc[1][3] = fmaf(qa.y, t1.w, acc[1][3]);
        }
#pragma unroll
        for (int i = 0; i < 2; i++) {
            float inv = 1.0f / fmaf(s, dens[(rm0 + i) * 4 + h], nnv);
#pragma unroll
            for (int j = 0; j < 4; j++)
                o[i][j] += fmaf(s, acc[i][j], vsum[h * 64 + cn0 + j]) * inv;
        }
    }
#pragma unroll
    for (int i = 0; i < 2; i++)
        *(float4*)(out + (size_t)(n0 + rm0 + i) * 64 + cn0) =
            make_float4(0.25f * o[i][0], 0.25f * o[i][1], 0.25f * o[i][2], 0.25f * o[i][3]);
}

// ================= GCN scatter (fp16 vmean gather) =================
__global__ void gcn_kernel(const int* __restrict__ ei, const float* __restrict__ ew,
                           float* __restrict__ out) {
    int gid = blockIdx.x * 256 + threadIdx.x;  // EE*16 threads, 16 per edge
    int e = gid >> 4, li = gid & 15;
    int row = ei[e];
    int col = ei[EE + e];
    float p = g_deg[col] * g_deg[row];
    float coeff = (p > 0.f) ? ew[e] * rsqrtf(p) : 0.f;
    uint2 hv = *(const uint2*)(g_vmeanh + (size_t)row * 64 + li * 4);
    float2 f01 = __half22float2(*(__half2*)&hv.x);
    float2 f23 = __half22float2(*(__half2*)&hv.y);
    float* dst = out + (size_t)col * 64 + li * 4;
    redg4(dst, coeff * f01.x, coeff * f01.y, coeff * f23.x, coeff * f23.y);
}

extern "C" void kernel_launch(void* const* d_in, const int* in_sizes, int n_in,
                              void* d_out, int out_size) {
    const float* Xq = (const float*)d_in[0];
    const float* Xs = (const float*)d_in[1];
    const float* ew = (const float*)d_in[2];
    const float* Wq = (const float*)d_in[3];
    const float* bq = (const float*)d_in[4];
    const float* Wk = (const float*)d_in[5];
    const float* bk = (const float*)d_in[6];
    const float* Wv = (const float*)d_in[7];
    const float* bv = (const float*)d_in[8];
    const int*   nn = (const int*)d_in[9];
    const int*   ei = (const int*)d_in[10];
    float* out = (float*)d_out;

    cudaFuncSetAttribute(att_kernel, cudaFuncAttributeMaxDynamicSharedMemorySize, ATT_SMEM);

    // order keeps proj in the ncu capture window (launch index 3)
    init_kernel<<<(ZTOT + 255) / 256, 256>>>();
    wconv_kernel<<<dim3(256, 3), 256>>>(Wq, Wk, Wv);
    deg_kernel<<<EE / 256, 256>>>(ei);
    proj_mma_kernel<<<dim3(2, 256, 3), 256>>>(Xq, Xs, bq, bk, bv);
    kv_kernel<<<dim3(BB * NH, 4), 256>>>();
    att_kernel<<<dim3(BB, 16), 256, ATT_SMEM>>>(nn, out);
    gcn_kernel<<<(EE * 16) / 256, 256>>>(ei, ew, out);
}